// round 1
// baseline (speedup 1.0000x reference)
#include <cuda_runtime.h>

#define BATCH 16
#define CIN   128
#define HGT   64
#define WID   384
#define F1C   128
#define F2C   96

#define W_TILE 64
#define H_TILE 2
#define CI     8
#define IN_ROWS 4
#define IN_COLS 66
#define IN_COLS_P 68

// scratch + folded parameters
__device__ float g_h1[(size_t)BATCH * F1C * HGT * WID];
__device__ float g_s0[CIN], g_t0[CIN];
__device__ float g_s1[F1C], g_d1[F1C];
__device__ float g_s2[F2C], g_d2[F2C];
__device__ float g_sf1;

__device__ __forceinline__ unsigned long long pack2(float lo, float hi) {
    unsigned long long r;
    asm("mov.b64 %0, {%1, %2};" : "=l"(r) : "f"(lo), "f"(hi));
    return r;
}
__device__ __forceinline__ void ffma2(unsigned long long& acc,
                                      unsigned long long a, unsigned long long b) {
    asm("fma.rn.f32x2 %0, %1, %2, %0;" : "+l"(acc) : "l"(a), "l"(b));
}
__device__ __forceinline__ void unpack2(unsigned long long v, float& lo, float& hi) {
    asm("mov.b64 {%0, %1}, %2;" : "=f"(lo), "=f"(hi) : "l"(v));
}

__global__ void prep_kernel(const float* __restrict__ Wv,
                            const float* __restrict__ bn0_g, const float* __restrict__ bn0_b,
                            const float* __restrict__ bn0_m, const float* __restrict__ bn0_v,
                            const float* __restrict__ conv1_b,
                            const float* __restrict__ bn1_g, const float* __restrict__ bn1_b,
                            const float* __restrict__ bn1_m, const float* __restrict__ bn1_v,
                            const float* __restrict__ conv2_b,
                            const float* __restrict__ bn2_g, const float* __restrict__ bn2_b,
                            const float* __restrict__ bn2_m, const float* __restrict__ bn2_v)
{
    int c = threadIdx.x;
    float w0 = Wv[0], w1 = Wv[1];
    float mx = fmaxf(w0, w1);
    float e0 = expf(w0 - mx), e1 = expf(w1 - mx);
    float inv = 1.f / (e0 + e1);
    float sf0 = e0 * inv, sf1 = e1 * inv;
    if (c == 0) g_sf1 = sf1;
    if (c < CIN) {
        float s = bn0_g[c] / sqrtf(bn0_v[c] + 1e-5f);
        g_s0[c] = s;
        g_t0[c] = bn0_b[c] - bn0_m[c] * s;
        float s1 = bn1_g[c] / sqrtf(bn1_v[c] + 1e-5f);
        g_s1[c] = s1;
        g_d1[c] = conv1_b[c] * s1 + bn1_b[c] - bn1_m[c] * s1;
    }
    if (c < F2C) {
        float s2 = bn2_g[c] / sqrtf(bn2_v[c] + 1e-5f);
        g_s2[c] = s2 * sf0;
        g_d2[c] = (conv2_b[c] * s2 + bn2_b[c] - bn2_m[c] * s2) * sf0;
    }
}

// Direct 3x3 'same' conv, NCHW. Block computes OC x H_TILE x W_TILE outputs.
// Each thread: 8 oc x 1 h x 8 w accumulated as 32 packed f32x2.
// FUSE_IN:  apply bn0+relu to the input while staging to smem (conv1).
// IS_FINAL: epilogue = bn2*sf0 + skip-gather (conv2); else bn1+relu -> g_h1.
template<int OC, bool FUSE_IN, bool IS_FINAL>
__global__ void __launch_bounds__((OC / 8) * 16)
conv3x3_kernel(const float* __restrict__ in, const float* __restrict__ wts,
               const float* __restrict__ xskip, float* __restrict__ out)
{
    constexpr int NOCG = OC / 8;
    constexpr int NTHR = NOCG * 16;

    __shared__ float s_in[CI][IN_ROWS][IN_COLS_P];
    __shared__ float s_w[CI * 9][OC + 1];   // +1 pad: conflict-free stores

    const int tid = threadIdx.x;
    const int wg  = tid & 7;               // 8 w-groups of 8
    const int ocg = (tid >> 3) % NOCG;     // oc groups of 8
    const int hh  = tid / (8 * NOCG);      // 0..1

    const int b   = blockIdx.z;
    const int h0  = blockIdx.y * H_TILE;
    const int w0  = blockIdx.x * W_TILE;
    const int oh  = h0 + hh;
    const int owb = w0 + wg * 8;

    unsigned long long acc[8][4];
    #pragma unroll
    for (int u = 0; u < 8; u++)
        #pragma unroll
        for (int p = 0; p < 4; p++) acc[u][p] = 0ULL;

    #pragma unroll 1
    for (int cc = 0; cc < CIN; cc += CI) {
        __syncthreads();
        // ---- stage input tile (with zero halo); fuse bn0+relu for conv1 ----
        for (int l = tid; l < CI * IN_ROWS * IN_COLS; l += NTHR) {
            int c   = l / (IN_ROWS * IN_COLS);
            int rem = l - c * (IN_ROWS * IN_COLS);
            int r   = rem / IN_COLS;
            int col = rem - r * IN_COLS;
            int gh  = h0 - 1 + r;
            int gw  = w0 - 1 + col;
            float v = 0.f;
            if ((unsigned)gh < (unsigned)HGT && (unsigned)gw < (unsigned)WID) {
                v = in[(((size_t)b * CIN + (cc + c)) * HGT + gh) * WID + gw];
                if (FUSE_IN)
                    v = fmaxf(0.f, fmaf(v, g_s0[cc + c], g_t0[cc + c]));
            }
            s_in[c][r][col] = v;
        }
        // ---- stage weight chunk: OIHW -> s_w[ic*9+k][oc] ----
        for (int l = tid; l < OC * CI * 9; l += NTHR) {
            int oc  = l / (CI * 9);
            int rem = l - oc * (CI * 9);
            s_w[rem][oc] = wts[((size_t)oc * CIN + cc) * 9 + rem];
        }
        __syncthreads();

        // ---- compute ----
        #pragma unroll 2
        for (int i = 0; i < CI; i++) {
            #pragma unroll
            for (int kh = 0; kh < 3; kh++) {
                float rin[10];
                #pragma unroll
                for (int j = 0; j < 10; j++) rin[j] = s_in[i][hh + kh][wg * 8 + j];
                #pragma unroll
                for (int kw = 0; kw < 3; kw++) {
                    unsigned long long ip[4];
                    #pragma unroll
                    for (int p = 0; p < 4; p++)
                        ip[p] = pack2(rin[2 * p + kw], rin[2 * p + kw + 1]);
                    const int row = (i * 3 + kh) * 3 + kw;
                    #pragma unroll
                    for (int u = 0; u < 8; u++) {
                        float wv = s_w[row][ocg * 8 + u];
                        unsigned long long wp = pack2(wv, wv);
                        #pragma unroll
                        for (int p = 0; p < 4; p++) ffma2(acc[u][p], ip[p], wp);
                    }
                }
            }
        }
    }

    // ---- epilogue ----
    if (!IS_FINAL) {
        #pragma unroll
        for (int u = 0; u < 8; u++) {
            const int oc = ocg * 8 + u;
            const float s = g_s1[oc], d = g_d1[oc];
            float* dst = out + (((size_t)b * OC + oc) * HGT + oh) * WID + owb;
            #pragma unroll
            for (int p = 0; p < 4; p++) {
                float lo, hi;
                unpack2(acc[u][p], lo, hi);
                float2 v2 = make_float2(fmaxf(0.f, fmaf(lo, s, d)),
                                        fmaxf(0.f, fmaf(hi, s, d)));
                *reinterpret_cast<float2*>(dst + 2 * p) = v2;
            }
        }
    } else {
        const float sf1 = g_sf1;
        #pragma unroll
        for (int u = 0; u < 8; u++) {
            const int oc = ocg * 8 + u;
            const int sc = (oc / 3) * 4 + (oc % 3);   // mask-gather channel
            const float s = g_s2[oc], d = g_d2[oc];
            const float* xp = xskip + (((size_t)b * CIN + sc) * HGT + oh) * WID + owb;
            float* dst = out + (((size_t)b * F2C + oc) * HGT + oh) * WID + owb;
            #pragma unroll
            for (int p = 0; p < 4; p++) {
                float lo, hi;
                unpack2(acc[u][p], lo, hi);
                float2 xs = *reinterpret_cast<const float2*>(xp + 2 * p);
                float2 v2 = make_float2(fmaf(lo, s, d) + sf1 * xs.x,
                                        fmaf(hi, s, d) + sf1 * xs.y);
                *reinterpret_cast<float2*>(dst + 2 * p) = v2;
            }
        }
    }
}

extern "C" void kernel_launch(void* const* d_in, const int* in_sizes, int n_in,
                              void* d_out, int out_size)
{
    const float* x       = (const float*)d_in[0];
    const float* Wv      = (const float*)d_in[1];
    const float* bn0_g   = (const float*)d_in[2];
    const float* bn0_b   = (const float*)d_in[3];
    const float* bn0_m   = (const float*)d_in[4];
    const float* bn0_v   = (const float*)d_in[5];
    const float* conv1_w = (const float*)d_in[6];
    const float* conv1_b = (const float*)d_in[7];
    const float* bn1_g   = (const float*)d_in[8];
    const float* bn1_b   = (const float*)d_in[9];
    const float* bn1_m   = (const float*)d_in[10];
    const float* bn1_v   = (const float*)d_in[11];
    const float* conv2_w = (const float*)d_in[12];
    const float* conv2_b = (const float*)d_in[13];
    const float* bn2_g   = (const float*)d_in[14];
    const float* bn2_b   = (const float*)d_in[15];
    const float* bn2_m   = (const float*)d_in[16];
    const float* bn2_v   = (const float*)d_in[17];

    float* h1 = nullptr;
    cudaGetSymbolAddress((void**)&h1, g_h1);

    prep_kernel<<<1, 128>>>(Wv, bn0_g, bn0_b, bn0_m, bn0_v, conv1_b,
                            bn1_g, bn1_b, bn1_m, bn1_v, conv2_b,
                            bn2_g, bn2_b, bn2_m, bn2_v);

    dim3 grid(WID / W_TILE, HGT / H_TILE, BATCH);   // 6 x 32 x 16
    conv3x3_kernel<F1C, true,  false><<<grid, (F1C / 8) * 16>>>(x,  conv1_w, nullptr, h1);
    conv3x3_kernel<F2C, false, true ><<<grid, (F2C / 8) * 16>>>(h1, conv2_w, x, (float*)d_out);
}

// round 3
// speedup vs baseline: 3.6727x; 3.6727x over previous
#include <cuda_runtime.h>
#include <cuda_fp16.h>
#include <cstdint>

#define BATCH 16
#define CIN   128
#define HGT   64
#define WID   384
#define F1C   128
#define F2C   96

#define TW     64            // output cols per block
#define TH     2             // output rows per block
#define ICB    16            // input channels per K-chunk
#define NCHUNK (CIN/ICB)     // 8
#define INROWS (TH+2)        // 4
#define INCOLS (TW+2)        // 66
#define CSTRIDE 24           // fp16 elems per (row,col) smem site (48B, conflict-free ldmatrix)

// ---------------- device globals (no allocs allowed) ----------------
__device__ __half g_h1[(size_t)BATCH * HGT * WID * F1C];          // NHWC fp16 scratch
__device__ __half g_w1[NCHUNK * 9 * ICB * F1C];                   // [chunk][tap][ic][oc]
__device__ __half g_w2[NCHUNK * 9 * ICB * F2C];
__device__ float g_s0[CIN], g_t0[CIN];
__device__ float g_s1[F1C], g_d1[F1C];
__device__ float g_s2[F2C], g_d2[F2C];
__device__ float g_sf1;

// ---------------- warp-MMA helpers ----------------
__device__ __forceinline__ void ldsm_x4(uint32_t* r, uint32_t addr) {
    asm volatile("ldmatrix.sync.aligned.m8n8.x4.shared.b16 {%0,%1,%2,%3}, [%4];\n"
                 : "=r"(r[0]), "=r"(r[1]), "=r"(r[2]), "=r"(r[3]) : "r"(addr));
}
__device__ __forceinline__ void ldsm_x4t(uint32_t* r, uint32_t addr) {
    asm volatile("ldmatrix.sync.aligned.m8n8.x4.trans.shared.b16 {%0,%1,%2,%3}, [%4];\n"
                 : "=r"(r[0]), "=r"(r[1]), "=r"(r[2]), "=r"(r[3]) : "r"(addr));
}
__device__ __forceinline__ void mma16816(float* c, const uint32_t* a, const uint32_t* b) {
    asm volatile("mma.sync.aligned.m16n8k16.row.col.f32.f16.f16.f32 "
                 "{%0,%1,%2,%3}, {%4,%5,%6,%7}, {%8,%9}, {%0,%1,%2,%3};\n"
                 : "+f"(c[0]), "+f"(c[1]), "+f"(c[2]), "+f"(c[3])
                 : "r"(a[0]), "r"(a[1]), "r"(a[2]), "r"(a[3]), "r"(b[0]), "r"(b[1]));
}

// ---------------- prep: fold BN/softmax + transpose weights to fp16 ----------------
__global__ void prep_kernel(const float* __restrict__ Wv,
                            const float* __restrict__ bn0_g, const float* __restrict__ bn0_b,
                            const float* __restrict__ bn0_m, const float* __restrict__ bn0_v,
                            const float* __restrict__ w1raw, const float* __restrict__ conv1_b,
                            const float* __restrict__ bn1_g, const float* __restrict__ bn1_b,
                            const float* __restrict__ bn1_m, const float* __restrict__ bn1_v,
                            const float* __restrict__ w2raw, const float* __restrict__ conv2_b,
                            const float* __restrict__ bn2_g, const float* __restrict__ bn2_b,
                            const float* __restrict__ bn2_m, const float* __restrict__ bn2_v)
{
    const int i = blockIdx.x * 256 + threadIdx.x;

    // scalar folds (block 0 only)
    if (blockIdx.x == 0 && threadIdx.x < 128) {
        const int c = threadIdx.x;
        float w0 = Wv[0], w1 = Wv[1];
        float mx = fmaxf(w0, w1);
        float e0 = expf(w0 - mx), e1 = expf(w1 - mx);
        float inv = 1.f / (e0 + e1);
        float sf0 = e0 * inv, sf1 = e1 * inv;
        if (c == 0) g_sf1 = sf1;
        {
            float s = bn0_g[c] * rsqrtf(bn0_v[c] + 1e-5f);
            g_s0[c] = s;
            g_t0[c] = bn0_b[c] - bn0_m[c] * s;
            float s1 = bn1_g[c] * rsqrtf(bn1_v[c] + 1e-5f);
            g_s1[c] = s1;
            g_d1[c] = conv1_b[c] * s1 + bn1_b[c] - bn1_m[c] * s1;
        }
        if (c < F2C) {
            float s2 = bn2_g[c] * rsqrtf(bn2_v[c] + 1e-5f);
            g_s2[c] = s2 * sf0;
            g_d2[c] = (conv2_b[c] * s2 + bn2_b[c] - bn2_m[c] * s2) * sf0;
        }
    }

    // weight transpose: OIHW fp32 -> [chunk][tap][ic][oc] fp16
    const int n1 = NCHUNK * 9 * ICB * F1C;
    if (i < n1) {
        int oc = i % F1C; int r = i / F1C;
        int ic = r % ICB; r /= ICB;
        int tap = r % 9;  int chunk = r / 9;
        g_w1[i] = __float2half(w1raw[((size_t)oc * CIN + chunk * ICB + ic) * 9 + tap]);
    }
    const int n2 = NCHUNK * 9 * ICB * F2C;
    if (i < n2) {
        int oc = i % F2C; int r = i / F2C;
        int ic = r % ICB; r /= ICB;
        int tap = r % 9;  int chunk = r / 9;
        g_w2[i] = __float2half(w2raw[((size_t)oc * F1C + chunk * ICB + ic) * 9 + tap]);
    }
}

// ---------------- implicit-GEMM 3x3 conv via mma.sync ----------------
// Block: 128 px (2 rows x 64 cols) x OC.  8 warps: 4 along px, 2 along oc.
// FIRST: input = x NCHW fp32, fuse bn0+relu, write h1 NHWC fp16 w/ bn1+relu.
// !FIRST: input = g_h1 NHWC fp16, epilogue bn2*sf0 + skip gather -> fp32 NCHW out.
template<int OC, int OCP, bool FIRST>
__global__ void __launch_bounds__(256)
conv_mma(const float* __restrict__ xin, const float* __restrict__ xskip,
         float* __restrict__ outf)
{
    extern __shared__ __half smem[];
    __half* s_in = smem;                                  // [4][66][24]
    __half* s_w  = smem + INROWS * INCOLS * CSTRIDE;      // [9][16][OCP]

    constexpr int NT8 = (OC / 2) / 8;   // n8 tiles per warp (8 or 6)
    constexpr int NG  = NT8 / 2;        // x4-trans loads per tap (4 or 3)

    const int tid  = threadIdx.x;
    const int lane = tid & 31;
    const int warp = tid >> 5;
    const int wm   = warp & 3;          // px quarter
    const int wn   = warp >> 2;         // oc half

    const int b  = blockIdx.z;
    const int h0 = blockIdx.y * TH;
    const int w0 = blockIdx.x * TW;

    float c[2][NT8][4];
    #pragma unroll
    for (int mt = 0; mt < 2; mt++)
        #pragma unroll
        for (int nt = 0; nt < NT8; nt++)
            #pragma unroll
            for (int k = 0; k < 4; k++) c[mt][nt][k] = 0.f;

    // per-thread ldmatrix base addresses
    const uint32_t s_in_b = (uint32_t)__cvta_generic_to_shared(s_in);
    const uint32_t s_w_b  = (uint32_t)__cvta_generic_to_shared(s_w);
    uint32_t a_base[2];
    #pragma unroll
    for (int mt = 0; mt < 2; mt++) {
        int pxb = wm * 32 + mt * 16;
        int r = pxb >> 6, cl = pxb & 63;
        a_base[mt] = s_in_b +
            (((r * INCOLS + cl + (lane & 15)) * CSTRIDE) + ((lane >> 4) << 3)) * 2;
    }
    const uint32_t b_base = s_w_b +
        (((lane & 15) * OCP) + wn * (OC / 2) + ((lane >> 4) << 3)) * 2;

    for (int cc = 0; cc < NCHUNK; cc++) {
        __syncthreads();

        // ---- stage input tile ----
        if (FIRST) {
            #pragma unroll 4
            for (int e = tid; e < ICB * INROWS * INCOLS; e += 256) {
                int ic  = e / (INROWS * INCOLS);
                int rem = e - ic * (INROWS * INCOLS);
                int r   = rem / INCOLS;
                int cl  = rem - r * INCOLS;
                int gh = h0 - 1 + r, gw = w0 - 1 + cl;
                float v = 0.f;
                if ((unsigned)gh < (unsigned)HGT && (unsigned)gw < (unsigned)WID) {
                    int gic = cc * ICB + ic;
                    v = xin[((size_t)(b * CIN + gic) * HGT + gh) * WID + gw];
                    v = fmaxf(0.f, fmaf(v, g_s0[gic], g_t0[gic]));
                }
                s_in[(r * INCOLS + cl) * CSTRIDE + ic] = __float2half(v);
            }
        } else {
            #pragma unroll 4
            for (int e = tid; e < INROWS * INCOLS * 2; e += 256) {
                int site = e >> 1, half = e & 1;
                int r = site / INCOLS, cl = site - r * INCOLS;
                int gh = h0 - 1 + r, gw = w0 - 1 + cl;
                uint4 v = make_uint4(0, 0, 0, 0);
                if ((unsigned)gh < (unsigned)HGT && (unsigned)gw < (unsigned)WID)
                    v = *reinterpret_cast<const uint4*>(
                        &g_h1[((size_t)((b * HGT + gh) * WID + gw)) * F1C + cc * ICB + half * 8]);
                *reinterpret_cast<uint4*>(&s_in[(r * INCOLS + cl) * CSTRIDE + half * 8]) = v;
            }
        }

        // ---- stage weights (already fp16 in target layout, just insert pad) ----
        {
            const __half* wsrc = (FIRST ? g_w1 : g_w2) + (size_t)cc * 9 * ICB * OC;
            #pragma unroll 4
            for (int e = tid; e < 9 * ICB * (OC / 8); e += 256) {
                int row = e / (OC / 8);
                int cb  = e - row * (OC / 8);
                *reinterpret_cast<uint4*>(&s_w[row * OCP + cb * 8]) =
                    *reinterpret_cast<const uint4*>(&wsrc[row * OC + cb * 8]);
            }
        }
        __syncthreads();

        // ---- 9 taps x k16 MMA ----
        #pragma unroll 3
        for (int tap = 0; tap < 9; tap++) {
            const int kh = tap / 3, kw = tap - kh * 3;
            const uint32_t aoff = (uint32_t)((kh * INCOLS + kw) * CSTRIDE * 2);
            uint32_t a[2][4];
            ldsm_x4(a[0], a_base[0] + aoff);
            ldsm_x4(a[1], a_base[1] + aoff);

            uint32_t bw[NT8][2];
            const uint32_t boff = b_base + (uint32_t)(tap * ICB * OCP * 2);
            #pragma unroll
            for (int g = 0; g < NG; g++)
                ldsm_x4t(&bw[2 * g][0], boff + (uint32_t)(g * 16 * 2));

            #pragma unroll
            for (int mt = 0; mt < 2; mt++)
                #pragma unroll
                for (int nt = 0; nt < NT8; nt++)
                    mma16816(c[mt][nt], a[mt], bw[nt]);
        }
    }

    // ---- epilogue ----
    const int px0 = wm * 32;
    if (FIRST) {
        #pragma unroll
        for (int mt = 0; mt < 2; mt++) {
            #pragma unroll
            for (int nt = 0; nt < NT8; nt++) {
                const int oc = wn * (OC / 2) + nt * 8 + (lane & 3) * 2;
                const float s0v = g_s1[oc],     d0v = g_d1[oc];
                const float s1v = g_s1[oc + 1], d1v = g_d1[oc + 1];
                #pragma unroll
                for (int e = 0; e < 2; e++) {
                    int p = px0 + mt * 16 + (lane >> 2) + e * 8;
                    int r = p >> 6, cw = p & 63;
                    int gh = h0 + r, gw = w0 + cw;
                    float v0 = fmaxf(0.f, fmaf(c[mt][nt][2 * e],     s0v, d0v));
                    float v1 = fmaxf(0.f, fmaf(c[mt][nt][2 * e + 1], s1v, d1v));
                    *reinterpret_cast<__half2*>(
                        &g_h1[((size_t)((b * HGT + gh) * WID + gw)) * F1C + oc]) =
                        __floats2half2_rn(v0, v1);
                }
            }
        }
    } else {
        const float sf1 = g_sf1;
        #pragma unroll
        for (int mt = 0; mt < 2; mt++) {
            #pragma unroll
            for (int nt = 0; nt < NT8; nt++) {
                const int oc = wn * (OC / 2) + nt * 8 + (lane & 3) * 2;
                #pragma unroll
                for (int e = 0; e < 2; e++) {
                    int p = px0 + mt * 16 + (lane >> 2) + e * 8;
                    int r = p >> 6, cw = p & 63;
                    int gh = h0 + r, gw = w0 + cw;
                    #pragma unroll
                    for (int j = 0; j < 2; j++) {
                        int occ = oc + j;
                        int sc  = (occ / 3) * 4 + (occ % 3);    // static mask gather
                        float v = fmaf(c[mt][nt][2 * e + j], g_s2[occ], g_d2[occ]);
                        v += sf1 * xskip[((size_t)(b * CIN + sc) * HGT + gh) * WID + gw];
                        outf[((size_t)(b * OC + occ) * HGT + gh) * WID + gw] = v;
                    }
                }
            }
        }
    }
}

// ---------------- launch ----------------
extern "C" void kernel_launch(void* const* d_in, const int* in_sizes, int n_in,
                              void* d_out, int out_size)
{
    const float* x       = (const float*)d_in[0];
    const float* Wv      = (const float*)d_in[1];
    const float* bn0_g   = (const float*)d_in[2];
    const float* bn0_b   = (const float*)d_in[3];
    const float* bn0_m   = (const float*)d_in[4];
    const float* bn0_v   = (const float*)d_in[5];
    const float* conv1_w = (const float*)d_in[6];
    const float* conv1_b = (const float*)d_in[7];
    const float* bn1_g   = (const float*)d_in[8];
    const float* bn1_b   = (const float*)d_in[9];
    const float* bn1_m   = (const float*)d_in[10];
    const float* bn1_v   = (const float*)d_in[11];
    const float* conv2_w = (const float*)d_in[12];
    const float* conv2_b = (const float*)d_in[13];
    const float* bn2_g   = (const float*)d_in[14];
    const float* bn2_b   = (const float*)d_in[15];
    const float* bn2_m   = (const float*)d_in[16];
    const float* bn2_v   = (const float*)d_in[17];

    const size_t smem1 = (size_t)(INROWS * INCOLS * CSTRIDE + 9 * ICB * 136) * 2;  // 51840
    const size_t smem2 = (size_t)(INROWS * INCOLS * CSTRIDE + 9 * ICB * 104) * 2;  // 42624
    cudaFuncSetAttribute(conv_mma<F1C, 136, true>,
                         cudaFuncAttributeMaxDynamicSharedMemorySize, (int)smem1);
    cudaFuncSetAttribute(conv_mma<F2C, 104, false>,
                         cudaFuncAttributeMaxDynamicSharedMemorySize, (int)smem2);

    prep_kernel<<<(NCHUNK * 9 * ICB * F1C + 255) / 256, 256>>>(
        Wv, bn0_g, bn0_b, bn0_m, bn0_v, conv1_w, conv1_b,
        bn1_g, bn1_b, bn1_m, bn1_v, conv2_w, conv2_b,
        bn2_g, bn2_b, bn2_m, bn2_v);

    dim3 grid(WID / TW, HGT / TH, BATCH);   // 6 x 32 x 16 = 3072
    conv_mma<F1C, 136, true ><<<grid, 256, smem1>>>(x, nullptr, nullptr);
    conv_mma<F2C, 104, false><<<grid, 256, smem2>>>(nullptr, x, (float*)d_out);
}

// round 7
// speedup vs baseline: 7.7448x; 2.1088x over previous
#include <cuda_runtime.h>
#include <cuda_fp16.h>
#include <cstdint>

#define BATCH 16
#define CIN   128
#define HGT   64
#define WID   384
#define F1C   128
#define F2C   96

#define TW     64
#define TH     2
#define ICB    16
#define NCHUNK (CIN/ICB)     // 8
#define INROWS (TH+2)        // 4
#define INCOLS (TW+2)        // 66
#define CSTRIDE 24           // fp16 per site (48B, conflict-free ldmatrix phases)
#define SIN_H  (INROWS*INCOLS*CSTRIDE)   // 6336 halves

#define NSITES (BATCH*HGT*WID)           // 393216
#define PRECONV_BLOCKS (NSITES/256)      // 1536
#define WFOLD_BLOCKS 576                 // ceil(8*9*16*128/256)

// ---------------- device globals ----------------
__device__ __half g_x [(size_t)NSITES * CIN];          // bn0+relu(x), NHWC fp16
__device__ __half g_h1[(size_t)NSITES * F1C];          // conv1 out, NHWC fp16
__device__ __half g_w1[NCHUNK * 9 * ICB * F1C];        // [chunk][tap][ic][oc]
__device__ __half g_w2[NCHUNK * 9 * ICB * F2C];
__device__ float g_s1[F1C], g_d1[F1C];
__device__ float g_s2[F2C], g_d2[F2C];
__device__ float g_sf1;

// ---------------- asm helpers ----------------
__device__ __forceinline__ void ldsm_x4(uint32_t* r, uint32_t addr) {
    asm volatile("ldmatrix.sync.aligned.m8n8.x4.shared.b16 {%0,%1,%2,%3}, [%4];\n"
                 : "=r"(r[0]), "=r"(r[1]), "=r"(r[2]), "=r"(r[3]) : "r"(addr));
}
__device__ __forceinline__ void ldsm_x4t(uint32_t* r, uint32_t addr) {
    asm volatile("ldmatrix.sync.aligned.m8n8.x4.trans.shared.b16 {%0,%1,%2,%3}, [%4];\n"
                 : "=r"(r[0]), "=r"(r[1]), "=r"(r[2]), "=r"(r[3]) : "r"(addr));
}
__device__ __forceinline__ void mma16816(float* c, const uint32_t* a, const uint32_t* b) {
    asm volatile("mma.sync.aligned.m16n8k16.row.col.f32.f16.f16.f32 "
                 "{%0,%1,%2,%3}, {%4,%5,%6,%7}, {%8,%9}, {%0,%1,%2,%3};\n"
                 : "+f"(c[0]), "+f"(c[1]), "+f"(c[2]), "+f"(c[3])
                 : "r"(a[0]), "r"(a[1]), "r"(a[2]), "r"(a[3]), "r"(b[0]), "r"(b[1]));
}
__device__ __forceinline__ void cp16(uint32_t dst, const void* src, bool pred) {
    int sz = pred ? 16 : 0;
    asm volatile("cp.async.cg.shared.global [%0], [%1], 16, %2;\n"
                 :: "r"(dst), "l"(src), "r"(sz));
}
__device__ __forceinline__ void cp_commit() {
    asm volatile("cp.async.commit_group;\n" ::: "memory");
}
__device__ __forceinline__ void cp_wait0() {
    asm volatile("cp.async.wait_group 0;\n" ::: "memory");
}

// ---------------- prep: preconv x + fold params + weight transpose ----------------
__global__ void prep_all(const float* __restrict__ x, const float* __restrict__ Wv,
                         const float* __restrict__ bn0_g, const float* __restrict__ bn0_b,
                         const float* __restrict__ bn0_m, const float* __restrict__ bn0_v,
                         const float* __restrict__ w1raw, const float* __restrict__ conv1_b,
                         const float* __restrict__ bn1_g, const float* __restrict__ bn1_b,
                         const float* __restrict__ bn1_m, const float* __restrict__ bn1_v,
                         const float* __restrict__ w2raw, const float* __restrict__ conv2_b,
                         const float* __restrict__ bn2_g, const float* __restrict__ bn2_b,
                         const float* __restrict__ bn2_m, const float* __restrict__ bn2_v)
{
    const int bid = blockIdx.x;
    const int tid = threadIdx.x;

    if (bid < PRECONV_BLOCKS) {
        // ---- bn0+relu(x) NCHW fp32 -> NHWC fp16 ----
        __shared__ float s0[CIN], t0[CIN];
        if (tid < CIN) {
            float s = bn0_g[tid] * rsqrtf(bn0_v[tid] + 1e-5f);
            s0[tid] = s;
            t0[tid] = bn0_b[tid] - bn0_m[tid] * s;
        }
        __syncthreads();
        const int id = bid * 256 + tid;              // site = (b*HGT+h)*WID+w
        const int w  = id % WID;
        const int t2 = id / WID;
        const int h  = t2 % HGT;
        const int b  = t2 / HGT;
        const float* src = x + ((size_t)(b * CIN) * HGT + h) * WID + w;
        __half* dst = g_x + (size_t)id * CIN;
        #pragma unroll 4
        for (int g = 0; g < CIN / 8; g++) {
            __half tmp[8];
            #pragma unroll
            for (int k = 0; k < 8; k++) {
                int ic = g * 8 + k;
                float v = src[(size_t)ic * (HGT * WID)];
                tmp[k] = __float2half(fmaxf(0.f, fmaf(v, s0[ic], t0[ic])));
            }
            *reinterpret_cast<uint4*>(dst + g * 8) = *reinterpret_cast<const uint4*>(tmp);
        }
        return;
    }

    const int wbid = bid - PRECONV_BLOCKS;
    if (wbid == 0 && tid < 128) {
        const int c = tid;
        float w0 = Wv[0], w1 = Wv[1];
        float mx = fmaxf(w0, w1);
        float e0 = expf(w0 - mx), e1 = expf(w1 - mx);
        float inv = 1.f / (e0 + e1);
        float sf0 = e0 * inv, sf1 = e1 * inv;
        if (c == 0) g_sf1 = sf1;
        {
            float s1 = bn1_g[c] * rsqrtf(bn1_v[c] + 1e-5f);
            g_s1[c] = s1;
            g_d1[c] = conv1_b[c] * s1 + bn1_b[c] - bn1_m[c] * s1;
        }
        if (c < F2C) {
            float s2 = bn2_g[c] * rsqrtf(bn2_v[c] + 1e-5f);
            g_s2[c] = s2 * sf0;
            g_d2[c] = (conv2_b[c] * s2 + bn2_b[c] - bn2_m[c] * s2) * sf0;
        }
    }
    const int i = wbid * 256 + tid;
    const int n1 = NCHUNK * 9 * ICB * F1C;
    if (i < n1) {
        int oc = i % F1C; int r = i / F1C;
        int ic = r % ICB; r /= ICB;
        int tap = r % 9;  int chunk = r / 9;
        g_w1[i] = __float2half(w1raw[((size_t)oc * CIN + chunk * ICB + ic) * 9 + tap]);
    }
    const int n2 = NCHUNK * 9 * ICB * F2C;
    if (i < n2) {
        int oc = i % F2C; int r = i / F2C;
        int ic = r % ICB; r /= ICB;
        int tap = r % 9;  int chunk = r / 9;
        g_w2[i] = __float2half(w2raw[((size_t)oc * F1C + chunk * ICB + ic) * 9 + tap]);
    }
}

// ---------------- double-buffered implicit-GEMM conv via mma.sync ----------------
// Input always NHWC fp16 (g_x or g_h1), 128 channels. Block: 128 px x OC, 8 warps.
template<int OC, int OCP, bool FIRST>
__global__ void __launch_bounds__(256, 2)
conv_mma(const __half* __restrict__ gin, const float* __restrict__ xskip,
         float* __restrict__ outf)
{
    extern __shared__ __half smem[];
    constexpr int SWH = 9 * ICB * OCP;          // weight halves per buffer
    constexpr int NT8 = (OC / 2) / 8;
    constexpr int NG  = NT8 / 2;

    const int tid  = threadIdx.x;
    const int lane = tid & 31;
    const int warp = tid >> 5;
    const int wm   = warp & 3;
    const int wn   = warp >> 2;

    const int b  = blockIdx.z;
    const int h0 = blockIdx.y * TH;
    const int w0 = blockIdx.x * TW;

    const uint32_t s_base = (uint32_t)__cvta_generic_to_shared(smem);
    const uint32_t W_BASE = (uint32_t)(2 * SIN_H * 2);          // byte offset of s_w buf0

    float c[2][NT8][4];
    #pragma unroll
    for (int mt = 0; mt < 2; mt++)
        #pragma unroll
        for (int nt = 0; nt < NT8; nt++)
            #pragma unroll
            for (int k = 0; k < 4; k++) c[mt][nt][k] = 0.f;

    // ldmatrix base addresses (relative to buffer 0)
    uint32_t a_base[2];
    #pragma unroll
    for (int mt = 0; mt < 2; mt++) {
        int pxb = wm * 32 + mt * 16;
        int r = pxb >> 6, cl = pxb & 63;
        a_base[mt] = s_base +
            (((r * INCOLS + cl + (lane & 15)) * CSTRIDE) + ((lane >> 4) << 3)) * 2;
    }
    const uint32_t b_base = s_base + W_BASE +
        (((lane & 15) * OCP) + wn * (OC / 2) + ((lane >> 4) << 3)) * 2;

    const __half* wbase = FIRST ? g_w1 : g_w2;

    // ---- stage chunk cc into buffer buf (async) ----
    auto stage = [&](int cc, int buf) {
        const uint32_t ib = s_base + (buf ? (uint32_t)(SIN_H * 2) : 0u);
        #pragma unroll
        for (int e0 = 0; e0 < 3; e0++) {
            int e = tid + e0 * 256;
            if (e < INROWS * INCOLS * 2) {
                int site = e >> 1, half = e & 1;
                int r  = site / INCOLS, cl = site - r * INCOLS;
                int gh = h0 - 1 + r, gw = w0 - 1 + cl;
                bool ok = ((unsigned)gh < (unsigned)HGT) && ((unsigned)gw < (unsigned)WID);
                const __half* src = gin +
                    ((size_t)((b * HGT + (ok ? gh : 0)) * WID + (ok ? gw : 0))) * CIN +
                    cc * ICB + half * 8;
                cp16(ib + (uint32_t)((site * CSTRIDE + half * 8) * 2), src, ok);
            }
        }
        const uint32_t wb = s_base + W_BASE + (buf ? (uint32_t)(SWH * 2) : 0u);
        const __half* wsrc = wbase + (size_t)cc * 9 * ICB * OC;
        constexpr int WN = 9 * ICB * (OC / 8);
        #pragma unroll
        for (int e0 = 0; e0 < (WN + 255) / 256; e0++) {
            int e = tid + e0 * 256;
            if (e < WN) {
                int row = e / (OC / 8), cb = e - row * (OC / 8);
                cp16(wb + (uint32_t)((row * OCP + cb * 8) * 2), wsrc + row * OC + cb * 8, true);
            }
        }
        cp_commit();
    };

    // ---- compute chunk in buffer buf ----
    auto compute = [&](int buf) {
        const uint32_t ioff = buf ? (uint32_t)(SIN_H * 2) : 0u;
        const uint32_t woff = buf ? (uint32_t)(SWH * 2) : 0u;
        #pragma unroll 3
        for (int tap = 0; tap < 9; tap++) {
            const int kh = tap / 3, kw = tap - kh * 3;
            const uint32_t aoff = (uint32_t)((kh * INCOLS + kw) * CSTRIDE * 2) + ioff;
            uint32_t a[2][4];
            ldsm_x4(a[0], a_base[0] + aoff);
            ldsm_x4(a[1], a_base[1] + aoff);

            uint32_t bw[NT8][2];
            const uint32_t boff = b_base + woff + (uint32_t)(tap * ICB * OCP * 2);
            #pragma unroll
            for (int g = 0; g < NG; g++)
                ldsm_x4t(&bw[2 * g][0], boff + (uint32_t)(g * 16 * 2));

            #pragma unroll
            for (int mt = 0; mt < 2; mt++)
                #pragma unroll
                for (int nt = 0; nt < NT8; nt++)
                    mma16816(c[mt][nt], a[mt], bw[nt]);
        }
    };

    // ---- pipelined mainloop: 1 barrier per chunk, prefetch overlaps compute ----
    stage(0, 0);
    #pragma unroll 1
    for (int cc = 0; cc < NCHUNK; cc++) {
        cp_wait0();
        __syncthreads();
        if (cc + 1 < NCHUNK) stage(cc + 1, (cc + 1) & 1);
        compute(cc & 1);
    }

    // ---- epilogue ----
    const int px0 = wm * 32;
    if (FIRST) {
        #pragma unroll
        for (int mt = 0; mt < 2; mt++) {
            #pragma unroll
            for (int nt = 0; nt < NT8; nt++) {
                const int oc = wn * (OC / 2) + nt * 8 + (lane & 3) * 2;
                const float s0v = g_s1[oc],     d0v = g_d1[oc];
                const float s1v = g_s1[oc + 1], d1v = g_d1[oc + 1];
                #pragma unroll
                for (int e = 0; e < 2; e++) {
                    int p = px0 + mt * 16 + (lane >> 2) + e * 8;
                    int r = p >> 6, cw = p & 63;
                    int gh = h0 + r, gw = w0 + cw;
                    float v0 = fmaxf(0.f, fmaf(c[mt][nt][2 * e],     s0v, d0v));
                    float v1 = fmaxf(0.f, fmaf(c[mt][nt][2 * e + 1], s1v, d1v));
                    *reinterpret_cast<__half2*>(
                        &g_h1[((size_t)((b * HGT + gh) * WID + gw)) * F1C + oc]) =
                        __floats2half2_rn(v0, v1);
                }
            }
        }
    } else {
        const float sf1 = g_sf1;
        #pragma unroll
        for (int mt = 0; mt < 2; mt++) {
            #pragma unroll
            for (int nt = 0; nt < NT8; nt++) {
                const int oc = wn * (OC / 2) + nt * 8 + (lane & 3) * 2;
                #pragma unroll
                for (int e = 0; e < 2; e++) {
                    int p = px0 + mt * 16 + (lane >> 2) + e * 8;
                    int r = p >> 6, cw = p & 63;
                    int gh = h0 + r, gw = w0 + cw;
                    #pragma unroll
                    for (int j = 0; j < 2; j++) {
                        int occ = oc + j;
                        int sc  = (occ / 3) * 4 + (occ % 3);
                        float v = fmaf(c[mt][nt][2 * e + j], g_s2[occ], g_d2[occ]);
                        v += sf1 * xskip[((size_t)(b * CIN + sc) * HGT + gh) * WID + gw];
                        outf[((size_t)(b * OC + occ) * HGT + gh) * WID + gw] = v;
                    }
                }
            }
        }
    }
}

// ---------------- launch ----------------
extern "C" void kernel_launch(void* const* d_in, const int* in_sizes, int n_in,
                              void* d_out, int out_size)
{
    const float* x       = (const float*)d_in[0];
    const float* Wv      = (const float*)d_in[1];
    const float* bn0_g   = (const float*)d_in[2];
    const float* bn0_b   = (const float*)d_in[3];
    const float* bn0_m   = (const float*)d_in[4];
    const float* bn0_v   = (const float*)d_in[5];
    const float* conv1_w = (const float*)d_in[6];
    const float* conv1_b = (const float*)d_in[7];
    const float* bn1_g   = (const float*)d_in[8];
    const float* bn1_b   = (const float*)d_in[9];
    const float* bn1_m   = (const float*)d_in[10];
    const float* bn1_v   = (const float*)d_in[11];
    const float* conv2_w = (const float*)d_in[12];
    const float* conv2_b = (const float*)d_in[13];
    const float* bn2_g   = (const float*)d_in[14];
    const float* bn2_b   = (const float*)d_in[15];
    const float* bn2_m   = (const float*)d_in[16];
    const float* bn2_v   = (const float*)d_in[17];

    __half *xh = nullptr, *h1 = nullptr;
    cudaGetSymbolAddress((void**)&xh, g_x);
    cudaGetSymbolAddress((void**)&h1, g_h1);

    const size_t smem1 = (size_t)(2 * SIN_H + 2 * 9 * ICB * 136) * 2;  // 103680 B
    const size_t smem2 = (size_t)(2 * SIN_H + 2 * 9 * ICB * 104) * 2;  //  85248 B
    cudaFuncSetAttribute(conv_mma<F1C, 136, true>,
                         cudaFuncAttributeMaxDynamicSharedMemorySize, (int)smem1);
    cudaFuncSetAttribute(conv_mma<F2C, 104, false>,
                         cudaFuncAttributeMaxDynamicSharedMemorySize, (int)smem2);

    prep_all<<<PRECONV_BLOCKS + WFOLD_BLOCKS, 256>>>(
        x, Wv, bn0_g, bn0_b, bn0_m, bn0_v, conv1_w, conv1_b,
        bn1_g, bn1_b, bn1_m, bn1_v, conv2_w, conv2_b,
        bn2_g, bn2_b, bn2_m, bn2_v);

    dim3 grid(WID / TW, HGT / TH, BATCH);   // 6 x 32 x 16 = 3072
    conv_mma<F1C, 136, true ><<<grid, 256, smem1>>>(xh, nullptr, nullptr);
    conv_mma<F2C, 104, false><<<grid, 256, smem2>>>(h1, x, (float*)d_out);
}